// round 15
// baseline (speedup 1.0000x reference)
#include <cuda_runtime.h>
#include <cuda_fp16.h>
#include <cstdint>

// Problem constants
#define Bsz   16384
#define HID   1024
#define MEM   1152

// GEMM tiling: 128x128 CTA tile, 8 warps (2x4), 64x32 warp tiles, fp16.
// Pipeline stage holds BK=64 as two BK=32 sub-tiles.
#define BM 128
#define BN 128
#define ROWB 64                      // bytes per smem row (32 halves)
#define SUB_B (BM*ROWB)              // 8192 B  (one sub-tile, A or B)
#define STAGE_B (4*SUB_B)            // 32768 B = [A0][A1][B0][B1]
#define NSTAGE 3
#define SMEM_BYTES (NSTAGE*STAGE_B)  // 98304 B

#define KT1 42                       // 2688/64
#define KT2 34                       // 2176/64

// Scratch (__device__ globals = allowed scratch)
__device__ __half g_c[(size_t)Bsz*2688];    // fp16 [input|h_prev|m_prev]
__device__ __half g_w1[(size_t)HID*2688];   // fp16 W_h
__device__ __half g_h[(size_t)Bsz*HID];     // fp16 h
__device__ float  g_y[(size_t)Bsz*HID];     // pre-LN GEMM1 output (fp32)
__device__ float  g_u[(size_t)Bsz*256];     // stage-2 GEMM output, stride 256 (fp32)
__device__ __half g_wcat[256*2176];         // packed fp16 small weights (rows 196..255 zero)
__device__ float  g_bcat[256];

// ---------------------------------------------------------------------------
__device__ __forceinline__ void mma16(float* c, const uint32_t* a, const uint32_t* b) {
    asm volatile(
        "mma.sync.aligned.m16n8k16.row.col.f32.f16.f16.f32 "
        "{%0,%1,%2,%3}, {%4,%5,%6,%7}, {%8,%9}, {%0,%1,%2,%3};\n"
        : "+f"(c[0]), "+f"(c[1]), "+f"(c[2]), "+f"(c[3])
        : "r"(a[0]), "r"(a[1]), "r"(a[2]), "r"(a[3]), "r"(b[0]), "r"(b[1]));
}

__device__ __forceinline__ void cp_async16(char* s, const char* g) {
    uint32_t sa = (uint32_t)__cvta_generic_to_shared(s);
    asm volatile("cp.async.cg.shared.global [%0], [%1], 16;\n" :: "r"(sa), "l"(g));
}
#define CP_COMMIT() asm volatile("cp.async.commit_group;\n" ::: "memory")
#define CP_WAIT0()  asm volatile("cp.async.wait_group 0;\n" ::: "memory")

#define U4C(v, i) (((const uint32_t*)&(v))[i])

// ---------------------------------------------------------------------------
// Unified prep kernel: one launch covering
//   blocks [0, 43008)        : concat+convert inputs -> g_c
//   blocks [43008, 45696)    : convert W_h -> g_w1
//   blocks [45696, 47362)    : pack+convert small weights -> g_wcat, g_bcat
// ---------------------------------------------------------------------------
#define PREP_CONCAT_BLKS 43008
#define PREP_WH_BLKS     2688
#define PREP_PACK_BLKS   1666   // ceil(196*2176 / 256)

__global__ __launch_bounds__(256)
void prep_kernel(const float4* __restrict__ X, const float4* __restrict__ H,
                 const float4* __restrict__ M, const float4* __restrict__ W,
                 const float* Wa, const float* ba,
                 const float* Wb, const float* bb,
                 const float* Wva, const float* bva,
                 const float* Wvb, const float* bvb) {
    const int blk = blockIdx.x;
    if (blk < PREP_CONCAT_BLKS) {
        int idx = blk * 256 + threadIdx.x;          // total 16384*672 float4s
        int b = idx / 672, c = idx - b * 672;
        float4 v;
        if (c < 128)      v = X[(size_t)b * 128 + c];
        else if (c < 384) v = H[(size_t)b * 256 + (c - 128)];
        else              v = M[(size_t)b * 288 + (c - 384)];
        __half2 lo = __floats2half2_rn(v.x, v.y);
        __half2 hi = __floats2half2_rn(v.z, v.w);
        ((uint2*)g_c)[idx] = make_uint2(*(uint32_t*)&lo, *(uint32_t*)&hi);
    } else if (blk < PREP_CONCAT_BLKS + PREP_WH_BLKS) {
        int idx = (blk - PREP_CONCAT_BLKS) * 256 + threadIdx.x;  // total 1024*672
        float4 v = W[idx];
        __half2 lo = __floats2half2_rn(v.x, v.y);
        __half2 hi = __floats2half2_rn(v.z, v.w);
        ((uint2*)g_w1)[idx] = make_uint2(*(uint32_t*)&lo, *(uint32_t*)&hi);
    } else {
        int idx = (blk - PREP_CONCAT_BLKS - PREP_WH_BLKS) * 256 + threadIdx.x;
        const int total = 196 * 2176;
        if (idx < total) {
            int n = idx / 2176, k = idx - n * 2176;
            const float* src; int r;
            if (n < 2)        { src = Wa;  r = n; }
            else if (n < 4)   { src = Wb;  r = n - 2; }
            else if (n < 100) { src = Wva; r = n - 4; }
            else              { src = Wvb; r = n - 100; }
            g_wcat[n * 2176 + k] = __float2half_rn(src[(size_t)r * 2176 + k]);
        }
        if (idx < 196) {
            int n = idx;
            float v;
            if (n < 2)        v = ba[n];
            else if (n < 4)   v = bb[n - 2];
            else if (n < 100) v = bva[n - 4];
            else              v = bvb[n - 100];
            g_bcat[n] = v;
        }
    }
}

// ---------------------------------------------------------------------------
// Per-stage fragment + MMA block (one BK=32 sub-tile). Validated k-permutation.
#define SUBTILE_MMA(As, Bs)                                                    \
    do {                                                                       \
        uint4 av[4][2]; uint4 bv[4];                                           \
        _Pragma("unroll")                                                      \
        for (int mi = 0; mi < 4; mi++) {                                       \
            av[mi][0] = *(const uint4*)((As) + mi * 16 * ROWB);                \
            av[mi][1] = *(const uint4*)((As) + (mi * 16 + 8) * ROWB);          \
        }                                                                      \
        _Pragma("unroll")                                                      \
        for (int ni = 0; ni < 4; ni++)                                         \
            bv[ni] = *(const uint4*)((Bs) + ni * 8 * ROWB);                    \
        _Pragma("unroll")                                                      \
        for (int j = 0; j < 2; j++) {                                          \
            _Pragma("unroll")                                                  \
            for (int mi = 0; mi < 4; mi++) {                                   \
                uint32_t a[4];                                                 \
                a[0] = U4C(av[mi][0], 2 * j);                                  \
                a[1] = U4C(av[mi][1], 2 * j);                                  \
                a[2] = U4C(av[mi][0], 2 * j + 1);                              \
                a[3] = U4C(av[mi][1], 2 * j + 1);                              \
                _Pragma("unroll")                                              \
                for (int ni = 0; ni < 4; ni++) {                               \
                    uint32_t b[2];                                             \
                    b[0] = U4C(bv[ni], 2 * j);                                 \
                    b[1] = U4C(bv[ni], 2 * j + 1);                             \
                    mma16(acc[mi][ni], a, b);                                  \
                }                                                              \
            }                                                                  \
        }                                                                      \
    } while (0)

#define ACC_INIT()                                                             \
    float acc[4][4][4];                                                        \
    _Pragma("unroll")                                                          \
    for (int i = 0; i < 4; i++)                                                \
        _Pragma("unroll")                                                      \
        for (int j = 0; j < 4; j++) {                                          \
            acc[i][j][0] = 0.f; acc[i][j][1] = 0.f;                            \
            acc[i][j][2] = 0.f; acc[i][j][3] = 0.f;                            \
        }

// ---------------------------------------------------------------------------
// GEMM body (R15): cp.async issue moved BETWEEN the two sub-tile MMA blocks.
//   WAIT0; sync; MMA(s0); ISSUE(t+1); COMMIT; MMA(s1)
// Hazard check: writes at iter t target stage (t+1)%3; after the top-of-iter
// sync no warp can still be reading stage t-1, and current reads are stage
// t%3 — distinct. wait_group 0 at top guarantees tile t fully resident.
#define GEMM_BODY(KT, ISSUE)                                                   \
    ACC_INIT()                                                                 \
    const uint32_t offA = (wm * 64 + lr) * ROWB + lc * 16;                     \
    const uint32_t offB = 2 * SUB_B + (wn * 32 + lr) * ROWB + lc * 16;         \
    ISSUE(0); CP_COMMIT();                                                     \
    int stg_i = 0;                                                             \
    for (int t = 0; t < KT; t++) {                                             \
        CP_WAIT0();                                                            \
        __syncthreads();                                                       \
        const char* stg = smem + stg_i * STAGE_B;                              \
        stg_i = (stg_i == NSTAGE - 1) ? 0 : stg_i + 1;                         \
        SUBTILE_MMA(stg + offA, stg + offB);                                   \
        if (t + 1 < KT) { ISSUE(t + 1); CP_COMMIT(); }                         \
        SUBTILE_MMA(stg + SUB_B + offA, stg + SUB_B + offB);                   \
    }

// ---------------------------------------------------------------------------
// GEMM1: Y = g_c @ g_w1^T + b_h   -> g_y
__global__ __launch_bounds__(256, 2)
void gemm1_kernel(const float* __restrict__ bias) {
    extern __shared__ __align__(128) char smem[];
    const int tid = threadIdx.x;
    const int bm = blockIdx.y, bn = blockIdx.x;
    const int warp = tid >> 5, lane = tid & 31;
    const int wm = warp >> 2, wn = warp & 3;
    const int lr = lane >> 2, lc = lane & 3;

    const uint32_t sOff = (tid >> 2) * ROWB + (tid & 3) * 16;
    const char* gA = (const char*)g_c  + ((size_t)(bm * BM) + (tid >> 2)) * 5376 + (tid & 3) * 16;
    const char* gB = (const char*)g_w1 + ((size_t)(bn * BN) + (tid >> 2)) * 5376 + (tid & 3) * 16;

#define ISSUE1(t) do {                                                         \
        char* st = smem + (((t) % NSTAGE)) * STAGE_B;                          \
        size_t ko = (size_t)(t) * 128;                                         \
        _Pragma("unroll")                                                      \
        for (int s = 0; s < 2; s++) {                                          \
            cp_async16(st + s * SUB_B + sOff,             gA + ko + s * 64);   \
            cp_async16(st + s * SUB_B + sOff + 64 * ROWB, gA + (size_t)64 * 5376 + ko + s * 64); \
            cp_async16(st + 2 * SUB_B + s * SUB_B + sOff, gB + ko + s * 64);   \
            cp_async16(st + 2 * SUB_B + s * SUB_B + sOff + 64 * ROWB,          \
                       gB + (size_t)64 * 5376 + ko + s * 64);                  \
        }                                                                      \
    } while (0)

    GEMM_BODY(KT1, ISSUE1)
#undef ISSUE1

    #pragma unroll
    for (int mi = 0; mi < 4; mi++) {
        #pragma unroll
        for (int ni = 0; ni < 4; ni++) {
            int r0 = bm * BM + wm * 64 + mi * 16 + lr;
            int c0 = bn * BN + wn * 32 + ni * 8 + 2 * lc;
            float b0 = bias[c0], b1 = bias[c0 + 1];
            float2 v0 = make_float2(acc[mi][ni][0] + b0, acc[mi][ni][1] + b1);
            float2 v1 = make_float2(acc[mi][ni][2] + b0, acc[mi][ni][3] + b1);
            *(float2*)&g_y[(size_t)r0 * HID + c0] = v0;
            *(float2*)&g_y[(size_t)(r0 + 8) * HID + c0] = v1;
        }
    }
}

// ---------------------------------------------------------------------------
// GEMM2: U = [g_h | g_c(m part)] @ g_wcat^T + g_bcat  -> g_u
__global__ __launch_bounds__(256, 2)
void gemm2_kernel() {
    extern __shared__ __align__(128) char smem[];
    const int tid = threadIdx.x;
    const int bm = blockIdx.y, bn = blockIdx.x;
    const int warp = tid >> 5, lane = tid & 31;
    const int wm = warp >> 2, wn = warp & 3;
    const int lr = lane >> 2, lc = lane & 3;

    const uint32_t sOff = (tid >> 2) * ROWB + (tid & 3) * 16;
    const char* gH = (const char*)g_h + ((size_t)(bm * BM) + (tid >> 2)) * 2048 + (tid & 3) * 16;
    const char* gC = (const char*)g_c + ((size_t)(bm * BM) + (tid >> 2)) * 5376 + 3072 + (tid & 3) * 16;
    const char* gW = (const char*)g_wcat + ((size_t)(bn * BN) + (tid >> 2)) * 4352 + (tid & 3) * 16;

#define ISSUE2(t) do {                                                         \
        char* st = smem + (((t) % NSTAGE)) * STAGE_B;                          \
        if ((t) < 16) {                                                        \
            size_t ko = (size_t)(t) * 128;                                     \
            _Pragma("unroll")                                                  \
            for (int s = 0; s < 2; s++) {                                      \
                cp_async16(st + s * SUB_B + sOff,             gH + ko + s * 64); \
                cp_async16(st + s * SUB_B + sOff + 64 * ROWB,                  \
                           gH + (size_t)64 * 2048 + ko + s * 64);              \
            }                                                                  \
        } else {                                                               \
            size_t ko = (size_t)((t) - 16) * 128;                              \
            _Pragma("unroll")                                                  \
            for (int s = 0; s < 2; s++) {                                      \
                cp_async16(st + s * SUB_B + sOff,             gC + ko + s * 64); \
                cp_async16(st + s * SUB_B + sOff + 64 * ROWB,                  \
                           gC + (size_t)64 * 5376 + ko + s * 64);              \
            }                                                                  \
        }                                                                      \
        size_t kw = (size_t)(t) * 128;                                         \
        _Pragma("unroll")                                                      \
        for (int s = 0; s < 2; s++) {                                          \
            cp_async16(st + 2 * SUB_B + s * SUB_B + sOff, gW + kw + s * 64);   \
            cp_async16(st + 2 * SUB_B + s * SUB_B + sOff + 64 * ROWB,          \
                       gW + (size_t)64 * 4352 + kw + s * 64);                  \
        }                                                                      \
    } while (0)

    GEMM_BODY(KT2, ISSUE2)
#undef ISSUE2

    #pragma unroll
    for (int mi = 0; mi < 4; mi++) {
        #pragma unroll
        for (int ni = 0; ni < 4; ni++) {
            int r0 = bm * BM + wm * 64 + mi * 16 + lr;
            int c0 = bn * BN + wn * 32 + ni * 8 + 2 * lc;
            float b0 = g_bcat[c0], b1 = g_bcat[c0 + 1];
            float2 v0 = make_float2(acc[mi][ni][0] + b0, acc[mi][ni][1] + b1);
            float2 v1 = make_float2(acc[mi][ni][2] + b0, acc[mi][ni][3] + b1);
            *(float2*)&g_u[(size_t)r0 * 256 + c0] = v0;
            *(float2*)&g_u[(size_t)(r0 + 8) * 256 + c0] = v1;
        }
    }
}

// ---------------------------------------------------------------------------
// LayerNorm + ReLU over rows of g_y -> hout (fp32 exact) and g_h (fp16)
__global__ __launch_bounds__(256)
void ln_relu_kernel(const float* __restrict__ g, const float* __restrict__ b,
                    float* __restrict__ hout) {
    __shared__ float sa[8], sb[8], smu[2];
    const int row = blockIdx.x, tid = threadIdx.x;
    const int lane = tid & 31, w = tid >> 5;

    float4 v = ((const float4*)(g_y + (size_t)row * HID))[tid];
    float s = v.x + v.y + v.z + v.w;
    float s2 = v.x * v.x + v.y * v.y + v.z * v.z + v.w * v.w;
    #pragma unroll
    for (int o = 16; o; o >>= 1) {
        s  += __shfl_down_sync(0xffffffffu, s, o);
        s2 += __shfl_down_sync(0xffffffffu, s2, o);
    }
    if (!lane) { sa[w] = s; sb[w] = s2; }
    __syncthreads();
    if (w == 0) {
        s  = (lane < 8) ? sa[lane] : 0.f;
        s2 = (lane < 8) ? sb[lane] : 0.f;
        #pragma unroll
        for (int o = 4; o; o >>= 1) {
            s  += __shfl_down_sync(0xffffffffu, s, o);
            s2 += __shfl_down_sync(0xffffffffu, s2, o);
        }
        if (!lane) {
            float mu = s * (1.f / HID);
            float var = s2 * (1.f / HID) - mu * mu;
            smu[0] = mu;
            smu[1] = rsqrtf(var + 1e-5f);
        }
    }
    __syncthreads();
    const float mu = smu[0], inv = smu[1];
    float4 gg = ((const float4*)g)[tid];
    float4 bb = ((const float4*)b)[tid];
    float4 o;
    o.x = fmaxf((v.x - mu) * inv * gg.x + bb.x, 0.f);
    o.y = fmaxf((v.y - mu) * inv * gg.y + bb.y, 0.f);
    o.z = fmaxf((v.z - mu) * inv * gg.z + bb.z, 0.f);
    o.w = fmaxf((v.w - mu) * inv * gg.w + bb.w, 0.f);
    ((float4*)(hout + (size_t)row * HID))[tid] = o;
    __half2 lo = __floats2half2_rn(o.x, o.y);
    __half2 hi = __floats2half2_rn(o.z, o.w);
    ((uint2*)(g_h + (size_t)row * HID))[tid] = make_uint2(*(uint32_t*)&lo, *(uint32_t*)&hi);
}

// ---------------------------------------------------------------------------
// Finalize: separable p-norm outer products -> m update
__global__ __launch_bounds__(128)
void finalize_kernel(const float* __restrict__ Mp, float* __restrict__ mout) {
    __shared__ float u[196];
    __shared__ float red[6];
    __shared__ float invn[4];
    __shared__ float cA[24], cB[24];
    const int row = blockIdx.x, tid = threadIdx.x;
    const int w = tid >> 5, lane = tid & 31;

    for (int i = tid; i < 196; i += 128) u[i] = g_u[(size_t)row * 256 + i];
    __syncthreads();

    auto p5 = [](float x) { float a = fabsf(x); float a2 = a * a; return a2 * a2 * a; };

    if (w == 0) {
        float lo = (lane < 24) ? p5(u[4 + lane]) : 0.f;
        float hi = (lane < 24) ? p5(u[4 + 24 + lane]) : 0.f;
        #pragma unroll
        for (int o = 16; o; o >>= 1) {
            lo += __shfl_down_sync(0xffffffffu, lo, o);
            hi += __shfl_down_sync(0xffffffffu, hi, o);
        }
        if (!lane) { red[0] = lo; red[1] = hi; }
    } else if (w == 1) {
        float x = p5(u[4 + 48 + lane]) + ((lane < 16) ? p5(u[4 + 80 + lane]) : 0.f);
        #pragma unroll
        for (int o = 16; o; o >>= 1) x += __shfl_down_sync(0xffffffffu, x, o);
        if (!lane) red[2] = x;
    } else if (w == 2) {
        float lo = (lane < 24) ? p5(u[100 + lane]) : 0.f;
        float hi = (lane < 24) ? p5(u[100 + 24 + lane]) : 0.f;
        #pragma unroll
        for (int o = 16; o; o >>= 1) {
            lo += __shfl_down_sync(0xffffffffu, lo, o);
            hi += __shfl_down_sync(0xffffffffu, hi, o);
        }
        if (!lane) { red[3] = lo; red[4] = hi; }
    } else {
        float x = p5(u[100 + 48 + lane]) + ((lane < 16) ? p5(u[100 + 80 + lane]) : 0.f);
        #pragma unroll
        for (int o = 16; o; o >>= 1) x += __shfl_down_sync(0xffffffffu, x, o);
        if (!lane) red[5] = x;
    }
    __syncthreads();

    if (tid < 4) {
        float s1 = (tid == 0) ? red[0] : (tid == 1) ? red[1] : (tid == 2) ? red[3] : red[4];
        float s2 = (tid < 2) ? red[2] : red[5];
        float nrm = powf(s1 * s2, 0.2f);
        invn[tid] = 1.f / fmaxf(nrm, 1e-12f);
    }
    __syncthreads();

    if (tid < 24) {
        cA[tid] = 0.5f * (u[0] * u[4 + tid] * invn[0] + u[1] * u[4 + 24 + tid] * invn[1]);
    } else if (tid >= 32 && tid < 56) {
        int i = tid - 32;
        cB[i] = 0.5f * (u[2] * u[100 + i] * invn[2] + u[3] * u[100 + 24 + i] * invn[3]);
    }
    __syncthreads();

    const float* mp = Mp + (size_t)row * MEM;
    float* mo = mout + (size_t)row * MEM;
    #pragma unroll
    for (int j = tid; j < MEM; j += 128) {
        int i = j / 48, j2 = j - i * 48;
        mo[j] = mp[j] + cA[i] * u[52 + j2] - cB[i] * u[148 + j2];
    }
}

// ---------------------------------------------------------------------------
extern "C" void kernel_launch(void* const* d_in, const int* in_sizes, int n_in,
                              void* d_out, int out_size) {
    const float* input  = (const float*)d_in[0];
    const float* h_prev = (const float*)d_in[1];
    const float* m_prev = (const float*)d_in[2];
    const float* W_h    = (const float*)d_in[3];
    const float* b_h    = (const float*)d_in[4];
    const float* ln_g   = (const float*)d_in[5];
    const float* ln_b   = (const float*)d_in[6];
    const float* W_a    = (const float*)d_in[7];
    const float* b_a    = (const float*)d_in[8];
    const float* W_b    = (const float*)d_in[9];
    const float* b_b    = (const float*)d_in[10];
    const float* W_va   = (const float*)d_in[11];
    const float* b_va   = (const float*)d_in[12];
    const float* W_vb   = (const float*)d_in[13];
    const float* b_vb   = (const float*)d_in[14];

    float* out  = (float*)d_out;
    float* hout = out;
    float* mout = out + (size_t)Bsz * HID;

    cudaFuncSetAttribute(gemm1_kernel, cudaFuncAttributeMaxDynamicSharedMemorySize, SMEM_BYTES);
    cudaFuncSetAttribute(gemm2_kernel, cudaFuncAttributeMaxDynamicSharedMemorySize, SMEM_BYTES);

    prep_kernel<<<PREP_CONCAT_BLKS + PREP_WH_BLKS + PREP_PACK_BLKS, 256>>>(
        (const float4*)input, (const float4*)h_prev, (const float4*)m_prev,
        (const float4*)W_h,
        W_a, b_a, W_b, b_b, W_va, b_va, W_vb, b_vb);
    gemm1_kernel<<<dim3(HID / BN, Bsz / BM), 256, SMEM_BYTES>>>(b_h);
    ln_relu_kernel<<<Bsz, 256>>>(ln_g, ln_b, hout);
    gemm2_kernel<<<dim3(2, Bsz / BM), 256, SMEM_BYTES>>>();
    finalize_kernel<<<Bsz, 128>>>(m_prev, mout);
}

// round 16
// speedup vs baseline: 1.0181x; 1.0181x over previous
#include <cuda_runtime.h>
#include <cuda_fp16.h>
#include <cstdint>

// Problem constants
#define Bsz   16384
#define HID   1024
#define MEM   1152

// GEMM tiling: 128x128 CTA tile, 8 warps (2x4), 64x32 warp tiles, fp16.
// Pipeline stage holds BK=64 as two BK=32 sub-tiles.
#define BM 128
#define BN 128
#define ROWB 64                      // bytes per smem row (32 halves)
#define SUB_B (BM*ROWB)              // 8192 B  (one sub-tile, A or B)
#define STAGE_B (4*SUB_B)            // 32768 B = [A0][A1][B0][B1]
#define NSTAGE 3
#define SMEM_BYTES (NSTAGE*STAGE_B)  // 98304 B

#define KT1 42                       // 2688/64
#define KT2 34                       // 2176/64

// Scratch (__device__ globals = allowed scratch)
__device__ __half g_c[(size_t)Bsz*2688];    // fp16 [input|h_prev|m_prev]
__device__ __half g_w1[(size_t)HID*2688];   // fp16 W_h
__device__ __half g_h[(size_t)Bsz*HID];     // fp16 h
__device__ float  g_y[(size_t)Bsz*HID];     // pre-LN GEMM1 output (fp32)
__device__ float  g_u[(size_t)Bsz*256];     // stage-2 GEMM output, stride 256 (fp32)
__device__ __half g_wcat[256*2176];         // packed fp16 small weights (rows 196..255 zero)
__device__ float  g_bcat[256];

// ---------------------------------------------------------------------------
__device__ __forceinline__ void mma16(float* c, const uint32_t* a, const uint32_t* b) {
    asm volatile(
        "mma.sync.aligned.m16n8k16.row.col.f32.f16.f16.f32 "
        "{%0,%1,%2,%3}, {%4,%5,%6,%7}, {%8,%9}, {%0,%1,%2,%3};\n"
        : "+f"(c[0]), "+f"(c[1]), "+f"(c[2]), "+f"(c[3])
        : "r"(a[0]), "r"(a[1]), "r"(a[2]), "r"(a[3]), "r"(b[0]), "r"(b[1]));
}

__device__ __forceinline__ void cp_async16(char* s, const char* g) {
    uint32_t sa = (uint32_t)__cvta_generic_to_shared(s);
    asm volatile("cp.async.cg.shared.global [%0], [%1], 16;\n" :: "r"(sa), "l"(g));
}
#define CP_COMMIT() asm volatile("cp.async.commit_group;\n" ::: "memory")
#define CP_WAIT1()  asm volatile("cp.async.wait_group 1;\n" ::: "memory")

#define U4C(v, i) (((const uint32_t*)&(v))[i])

// ---------------------------------------------------------------------------
// Unified prep kernel: one launch covering
//   blocks [0, 43008)        : concat+convert inputs -> g_c
//   blocks [43008, 45696)    : convert W_h -> g_w1
//   blocks [45696, 47362)    : pack+convert small weights -> g_wcat, g_bcat
// ---------------------------------------------------------------------------
#define PREP_CONCAT_BLKS 43008
#define PREP_WH_BLKS     2688
#define PREP_PACK_BLKS   1666   // ceil(196*2176 / 256)

__global__ __launch_bounds__(256)
void prep_kernel(const float4* __restrict__ X, const float4* __restrict__ H,
                 const float4* __restrict__ M, const float4* __restrict__ W,
                 const float* Wa, const float* ba,
                 const float* Wb, const float* bb,
                 const float* Wva, const float* bva,
                 const float* Wvb, const float* bvb) {
    const int blk = blockIdx.x;
    if (blk < PREP_CONCAT_BLKS) {
        int idx = blk * 256 + threadIdx.x;          // total 16384*672 float4s
        int b = idx / 672, c = idx - b * 672;
        float4 v;
        if (c < 128)      v = X[(size_t)b * 128 + c];
        else if (c < 384) v = H[(size_t)b * 256 + (c - 128)];
        else              v = M[(size_t)b * 288 + (c - 384)];
        __half2 lo = __floats2half2_rn(v.x, v.y);
        __half2 hi = __floats2half2_rn(v.z, v.w);
        ((uint2*)g_c)[idx] = make_uint2(*(uint32_t*)&lo, *(uint32_t*)&hi);
    } else if (blk < PREP_CONCAT_BLKS + PREP_WH_BLKS) {
        int idx = (blk - PREP_CONCAT_BLKS) * 256 + threadIdx.x;  // total 1024*672
        float4 v = W[idx];
        __half2 lo = __floats2half2_rn(v.x, v.y);
        __half2 hi = __floats2half2_rn(v.z, v.w);
        ((uint2*)g_w1)[idx] = make_uint2(*(uint32_t*)&lo, *(uint32_t*)&hi);
    } else {
        int idx = (blk - PREP_CONCAT_BLKS - PREP_WH_BLKS) * 256 + threadIdx.x;
        const int total = 196 * 2176;
        if (idx < total) {
            int n = idx / 2176, k = idx - n * 2176;
            const float* src; int r;
            if (n < 2)        { src = Wa;  r = n; }
            else if (n < 4)   { src = Wb;  r = n - 2; }
            else if (n < 100) { src = Wva; r = n - 4; }
            else              { src = Wvb; r = n - 100; }
            g_wcat[n * 2176 + k] = __float2half_rn(src[(size_t)r * 2176 + k]);
        }
        if (idx < 196) {
            int n = idx;
            float v;
            if (n < 2)        v = ba[n];
            else if (n < 4)   v = bb[n - 2];
            else if (n < 100) v = bva[n - 4];
            else              v = bvb[n - 100];
            g_bcat[n] = v;
        }
    }
}

// ---------------------------------------------------------------------------
// Per-stage fragment + MMA block (one BK=32 sub-tile). Validated k-permutation.
#define SUBTILE_MMA(As, Bs)                                                    \
    do {                                                                       \
        uint4 av[4][2]; uint4 bv[4];                                           \
        _Pragma("unroll")                                                      \
        for (int mi = 0; mi < 4; mi++) {                                       \
            av[mi][0] = *(const uint4*)((As) + mi * 16 * ROWB);                \
            av[mi][1] = *(const uint4*)((As) + (mi * 16 + 8) * ROWB);          \
        }                                                                      \
        _Pragma("unroll")                                                      \
        for (int ni = 0; ni < 4; ni++)                                         \
            bv[ni] = *(const uint4*)((Bs) + ni * 8 * ROWB);                    \
        _Pragma("unroll")                                                      \
        for (int j = 0; j < 2; j++) {                                          \
            _Pragma("unroll")                                                  \
            for (int mi = 0; mi < 4; mi++) {                                   \
                uint32_t a[4];                                                 \
                a[0] = U4C(av[mi][0], 2 * j);                                  \
                a[1] = U4C(av[mi][1], 2 * j);                                  \
                a[2] = U4C(av[mi][0], 2 * j + 1);                              \
                a[3] = U4C(av[mi][1], 2 * j + 1);                              \
                _Pragma("unroll")                                              \
                for (int ni = 0; ni < 4; ni++) {                               \
                    uint32_t b[2];                                             \
                    b[0] = U4C(bv[ni], 2 * j);                                 \
                    b[1] = U4C(bv[ni], 2 * j + 1);                             \
                    mma16(acc[mi][ni], a, b);                                  \
                }                                                              \
            }                                                                  \
        }                                                                      \
    } while (0)

#define ACC_INIT()                                                             \
    float acc[4][4][4];                                                        \
    _Pragma("unroll")                                                          \
    for (int i = 0; i < 4; i++)                                                \
        _Pragma("unroll")                                                      \
        for (int j = 0; j < 4; j++) {                                          \
            acc[i][j][0] = 0.f; acc[i][j][1] = 0.f;                            \
            acc[i][j][2] = 0.f; acc[i][j][3] = 0.f;                            \
        }

// ---------------------------------------------------------------------------
// GEMM body (R16): two-tile prologue + wait_group 1 (R14's full lookahead)
// with the cp.async issue placed between the two sub-tile MMA blocks.
//   prologue: ISSUE(0); COMMIT; ISSUE(1); COMMIT
//   iter t:   WAIT1; sync; MMA(s0); ISSUE(t+2); COMMIT; MMA(s1)
// Hazards (NSTAGE=3): iter t reads stage t%3, writes (t+2)%3 — distinct.
// Straggler in iter t-1 reads (t-1)%3 == (t+2)%3, but issue is AFTER the
// barrier which no warp passes until all finish iter t-1 — safe.
// WAIT1 with groups {t, t+1} outstanding => tile t resident, t+1 in flight.
#define GEMM_BODY(KT, ISSUE)                                                   \
    ACC_INIT()                                                                 \
    const uint32_t offA = (wm * 64 + lr) * ROWB + lc * 16;                     \
    const uint32_t offB = 2 * SUB_B + (wn * 32 + lr) * ROWB + lc * 16;         \
    ISSUE(0); CP_COMMIT();                                                     \
    ISSUE(1); CP_COMMIT();                                                     \
    int stg_i = 0;                                                             \
    for (int t = 0; t < KT; t++) {                                             \
        CP_WAIT1();                                                            \
        __syncthreads();                                                       \
        const char* stg = smem + stg_i * STAGE_B;                              \
        stg_i = (stg_i == NSTAGE - 1) ? 0 : stg_i + 1;                         \
        SUBTILE_MMA(stg + offA, stg + offB);                                   \
        if (t + 2 < KT) { ISSUE(t + 2); }                                      \
        CP_COMMIT();                                                           \
        SUBTILE_MMA(stg + SUB_B + offA, stg + SUB_B + offB);                   \
    }

// ---------------------------------------------------------------------------
// GEMM1: Y = g_c @ g_w1^T + b_h   -> g_y
__global__ __launch_bounds__(256, 2)
void gemm1_kernel(const float* __restrict__ bias) {
    extern __shared__ __align__(128) char smem[];
    const int tid = threadIdx.x;
    const int bm = blockIdx.y, bn = blockIdx.x;
    const int warp = tid >> 5, lane = tid & 31;
    const int wm = warp >> 2, wn = warp & 3;
    const int lr = lane >> 2, lc = lane & 3;

    const uint32_t sOff = (tid >> 2) * ROWB + (tid & 3) * 16;
    const char* gA = (const char*)g_c  + ((size_t)(bm * BM) + (tid >> 2)) * 5376 + (tid & 3) * 16;
    const char* gB = (const char*)g_w1 + ((size_t)(bn * BN) + (tid >> 2)) * 5376 + (tid & 3) * 16;

#define ISSUE1(t) do {                                                         \
        char* st = smem + (((t) % NSTAGE)) * STAGE_B;                          \
        size_t ko = (size_t)(t) * 128;                                         \
        _Pragma("unroll")                                                      \
        for (int s = 0; s < 2; s++) {                                          \
            cp_async16(st + s * SUB_B + sOff,             gA + ko + s * 64);   \
            cp_async16(st + s * SUB_B + sOff + 64 * ROWB, gA + (size_t)64 * 5376 + ko + s * 64); \
            cp_async16(st + 2 * SUB_B + s * SUB_B + sOff, gB + ko + s * 64);   \
            cp_async16(st + 2 * SUB_B + s * SUB_B + sOff + 64 * ROWB,          \
                       gB + (size_t)64 * 5376 + ko + s * 64);                  \
        }                                                                      \
    } while (0)

    GEMM_BODY(KT1, ISSUE1)
#undef ISSUE1

    #pragma unroll
    for (int mi = 0; mi < 4; mi++) {
        #pragma unroll
        for (int ni = 0; ni < 4; ni++) {
            int r0 = bm * BM + wm * 64 + mi * 16 + lr;
            int c0 = bn * BN + wn * 32 + ni * 8 + 2 * lc;
            float b0 = bias[c0], b1 = bias[c0 + 1];
            float2 v0 = make_float2(acc[mi][ni][0] + b0, acc[mi][ni][1] + b1);
            float2 v1 = make_float2(acc[mi][ni][2] + b0, acc[mi][ni][3] + b1);
            *(float2*)&g_y[(size_t)r0 * HID + c0] = v0;
            *(float2*)&g_y[(size_t)(r0 + 8) * HID + c0] = v1;
        }
    }
}

// ---------------------------------------------------------------------------
// GEMM2: U = [g_h | g_c(m part)] @ g_wcat^T + g_bcat  -> g_u
__global__ __launch_bounds__(256, 2)
void gemm2_kernel() {
    extern __shared__ __align__(128) char smem[];
    const int tid = threadIdx.x;
    const int bm = blockIdx.y, bn = blockIdx.x;
    const int warp = tid >> 5, lane = tid & 31;
    const int wm = warp >> 2, wn = warp & 3;
    const int lr = lane >> 2, lc = lane & 3;

    const uint32_t sOff = (tid >> 2) * ROWB + (tid & 3) * 16;
    const char* gH = (const char*)g_h + ((size_t)(bm * BM) + (tid >> 2)) * 2048 + (tid & 3) * 16;
    const char* gC = (const char*)g_c + ((size_t)(bm * BM) + (tid >> 2)) * 5376 + 3072 + (tid & 3) * 16;
    const char* gW = (const char*)g_wcat + ((size_t)(bn * BN) + (tid >> 2)) * 4352 + (tid & 3) * 16;

#define ISSUE2(t) do {                                                         \
        char* st = smem + (((t) % NSTAGE)) * STAGE_B;                          \
        if ((t) < 16) {                                                        \
            size_t ko = (size_t)(t) * 128;                                     \
            _Pragma("unroll")                                                  \
            for (int s = 0; s < 2; s++) {                                      \
                cp_async16(st + s * SUB_B + sOff,             gH + ko + s * 64); \
                cp_async16(st + s * SUB_B + sOff + 64 * ROWB,                  \
                           gH + (size_t)64 * 2048 + ko + s * 64);              \
            }                                                                  \
        } else {                                                               \
            size_t ko = (size_t)((t) - 16) * 128;                              \
            _Pragma("unroll")                                                  \
            for (int s = 0; s < 2; s++) {                                      \
                cp_async16(st + s * SUB_B + sOff,             gC + ko + s * 64); \
                cp_async16(st + s * SUB_B + sOff + 64 * ROWB,                  \
                           gC + (size_t)64 * 5376 + ko + s * 64);              \
            }                                                                  \
        }                                                                      \
        size_t kw = (size_t)(t) * 128;                                         \
        _Pragma("unroll")                                                      \
        for (int s = 0; s < 2; s++) {                                          \
            cp_async16(st + 2 * SUB_B + s * SUB_B + sOff, gW + kw + s * 64);   \
            cp_async16(st + 2 * SUB_B + s * SUB_B + sOff + 64 * ROWB,          \
                       gW + (size_t)64 * 4352 + kw + s * 64);                  \
        }                                                                      \
    } while (0)

    GEMM_BODY(KT2, ISSUE2)
#undef ISSUE2

    #pragma unroll
    for (int mi = 0; mi < 4; mi++) {
        #pragma unroll
        for (int ni = 0; ni < 4; ni++) {
            int r0 = bm * BM + wm * 64 + mi * 16 + lr;
            int c0 = bn * BN + wn * 32 + ni * 8 + 2 * lc;
            float b0 = g_bcat[c0], b1 = g_bcat[c0 + 1];
            float2 v0 = make_float2(acc[mi][ni][0] + b0, acc[mi][ni][1] + b1);
            float2 v1 = make_float2(acc[mi][ni][2] + b0, acc[mi][ni][3] + b1);
            *(float2*)&g_u[(size_t)r0 * 256 + c0] = v0;
            *(float2*)&g_u[(size_t)(r0 + 8) * 256 + c0] = v1;
        }
    }
}

// ---------------------------------------------------------------------------
// LayerNorm + ReLU over rows of g_y -> hout (fp32 exact) and g_h (fp16)
__global__ __launch_bounds__(256)
void ln_relu_kernel(const float* __restrict__ g, const float* __restrict__ b,
                    float* __restrict__ hout) {
    __shared__ float sa[8], sb[8], smu[2];
    const int row = blockIdx.x, tid = threadIdx.x;
    const int lane = tid & 31, w = tid >> 5;

    float4 v = ((const float4*)(g_y + (size_t)row * HID))[tid];
    float s = v.x + v.y + v.z + v.w;
    float s2 = v.x * v.x + v.y * v.y + v.z * v.z + v.w * v.w;
    #pragma unroll
    for (int o = 16; o; o >>= 1) {
        s  += __shfl_down_sync(0xffffffffu, s, o);
        s2 += __shfl_down_sync(0xffffffffu, s2, o);
    }
    if (!lane) { sa[w] = s; sb[w] = s2; }
    __syncthreads();
    if (w == 0) {
        s  = (lane < 8) ? sa[lane] : 0.f;
        s2 = (lane < 8) ? sb[lane] : 0.f;
        #pragma unroll
        for (int o = 4; o; o >>= 1) {
            s  += __shfl_down_sync(0xffffffffu, s, o);
            s2 += __shfl_down_sync(0xffffffffu, s2, o);
        }
        if (!lane) {
            float mu = s * (1.f / HID);
            float var = s2 * (1.f / HID) - mu * mu;
            smu[0] = mu;
            smu[1] = rsqrtf(var + 1e-5f);
        }
    }
    __syncthreads();
    const float mu = smu[0], inv = smu[1];
    float4 gg = ((const float4*)g)[tid];
    float4 bb = ((const float4*)b)[tid];
    float4 o;
    o.x = fmaxf((v.x - mu) * inv * gg.x + bb.x, 0.f);
    o.y = fmaxf((v.y - mu) * inv * gg.y + bb.y, 0.f);
    o.z = fmaxf((v.z - mu) * inv * gg.z + bb.z, 0.f);
    o.w = fmaxf((v.w - mu) * inv * gg.w + bb.w, 0.f);
    ((float4*)(hout + (size_t)row * HID))[tid] = o;
    __half2 lo = __floats2half2_rn(o.x, o.y);
    __half2 hi = __floats2half2_rn(o.z, o.w);
    ((uint2*)(g_h + (size_t)row * HID))[tid] = make_uint2(*(uint32_t*)&lo, *(uint32_t*)&hi);
}

// ---------------------------------------------------------------------------
// Finalize: separable p-norm outer products -> m update
__global__ __launch_bounds__(128)
void finalize_kernel(const float* __restrict__ Mp, float* __restrict__ mout) {
    __shared__ float u[196];
    __shared__ float red[6];
    __shared__ float invn[4];
    __shared__ float cA[24], cB[24];
    const int row = blockIdx.x, tid = threadIdx.x;
    const int w = tid >> 5, lane = tid & 31;

    for (int i = tid; i < 196; i += 128) u[i] = g_u[(size_t)row * 256 + i];
    __syncthreads();

    auto p5 = [](float x) { float a = fabsf(x); float a2 = a * a; return a2 * a2 * a; };

    if (w == 0) {
        float lo = (lane < 24) ? p5(u[4 + lane]) : 0.f;
        float hi = (lane < 24) ? p5(u[4 + 24 + lane]) : 0.f;
        #pragma unroll
        for (int o = 16; o; o >>= 1) {
            lo += __shfl_down_sync(0xffffffffu, lo, o);
            hi += __shfl_down_sync(0xffffffffu, hi, o);
        }
        if (!lane) { red[0] = lo; red[1] = hi; }
    } else if (w == 1) {
        float x = p5(u[4 + 48 + lane]) + ((lane < 16) ? p5(u[4 + 80 + lane]) : 0.f);
        #pragma unroll
        for (int o = 16; o; o >>= 1) x += __shfl_down_sync(0xffffffffu, x, o);
        if (!lane) red[2] = x;
    } else if (w == 2) {
        float lo = (lane < 24) ? p5(u[100 + lane]) : 0.f;
        float hi = (lane < 24) ? p5(u[100 + 24 + lane]) : 0.f;
        #pragma unroll
        for (int o = 16; o; o >>= 1) {
            lo += __shfl_down_sync(0xffffffffu, lo, o);
            hi += __shfl_down_sync(0xffffffffu, hi, o);
        }
        if (!lane) { red[3] = lo; red[4] = hi; }
    } else {
        float x = p5(u[100 + 48 + lane]) + ((lane < 16) ? p5(u[100 + 80 + lane]) : 0.f);
        #pragma unroll
        for (int o = 16; o; o >>= 1) x += __shfl_down_sync(0xffffffffu, x, o);
        if (!lane) red[5] = x;
    }
    __syncthreads();

    if (tid < 4) {
        float s1 = (tid == 0) ? red[0] : (tid == 1) ? red[1] : (tid == 2) ? red[3] : red[4];
        float s2 = (tid < 2) ? red[2] : red[5];
        float nrm = powf(s1 * s2, 0.2f);
        invn[tid] = 1.f / fmaxf(nrm, 1e-12f);
    }
    __syncthreads();

    if (tid < 24) {
        cA[tid] = 0.5f * (u[0] * u[4 + tid] * invn[0] + u[1] * u[4 + 24 + tid] * invn[1]);
    } else if (tid >= 32 && tid < 56) {
        int i = tid - 32;
        cB[i] = 0.5f * (u[2] * u[100 + i] * invn[2] + u[3] * u[100 + 24 + i] * invn[3]);
    }
    __syncthreads();

    const float* mp = Mp + (size_t)row * MEM;
    float* mo = mout + (size_t)row * MEM;
    #pragma unroll
    for (int j = tid; j < MEM; j += 128) {
        int i = j / 48, j2 = j - i * 48;
        mo[j] = mp[j] + cA[i] * u[52 + j2] - cB[i] * u[148 + j2];
    }
}

// ---------------------------------------------------------------------------
extern "C" void kernel_launch(void* const* d_in, const int* in_sizes, int n_in,
                              void* d_out, int out_size) {
    const float* input  = (const float*)d_in[0];
    const float* h_prev = (const float*)d_in[1];
    const float* m_prev = (const float*)d_in[2];
    const float* W_h    = (const float*)d_in[3];
    const float* b_h    = (const float*)d_in[4];
    const float* ln_g   = (const float*)d_in[5];
    const float* ln_b   = (const float*)d_in[6];
    const float* W_a    = (const float*)d_in[7];
    const float* b_a    = (const float*)d_in[8];
    const float* W_b    = (const float*)d_in[9];
    const float* b_b    = (const float*)d_in[10];
    const float* W_va   = (const float*)d_in[11];
    const float* b_va   = (const float*)d_in[12];
    const float* W_vb   = (const float*)d_in[13];
    const float* b_vb   = (const float*)d_in[14];

    float* out  = (float*)d_out;
    float* hout = out;
    float* mout = out + (size_t)Bsz * HID;

    cudaFuncSetAttribute(gemm1_kernel, cudaFuncAttributeMaxDynamicSharedMemorySize, SMEM_BYTES);
    cudaFuncSetAttribute(gemm2_kernel, cudaFuncAttributeMaxDynamicSharedMemorySize, SMEM_BYTES);

    prep_kernel<<<PREP_CONCAT_BLKS + PREP_WH_BLKS + PREP_PACK_BLKS, 256>>>(
        (const float4*)input, (const float4*)h_prev, (const float4*)m_prev,
        (const float4*)W_h,
        W_a, b_a, W_b, b_b, W_va, b_va, W_vb, b_vb);
    gemm1_kernel<<<dim3(HID / BN, Bsz / BM), 256, SMEM_BYTES>>>(b_h);
    ln_relu_kernel<<<Bsz, 256>>>(ln_g, ln_b, hout);
    gemm2_kernel<<<dim3(2, Bsz / BM), 256, SMEM_BYTES>>>();
    finalize_kernel<<<Bsz, 128>>>(m_prev, mout);
}

// round 17
// speedup vs baseline: 1.0652x; 1.0462x over previous
#include <cuda_runtime.h>
#include <cuda_fp16.h>
#include <cstdint>

// Problem constants
#define Bsz   16384
#define HID   1024
#define MEM   1152

// GEMM tiling: 128x128 CTA tile, 8 warps (2x4), 64x32 warp tiles, fp16.
// Pipeline stage holds BK=64 as two BK=32 sub-tiles.
#define BM 128
#define BN 128
#define ROWB 64                      // bytes per smem row (32 halves)
#define SUB_B (BM*ROWB)              // 8192 B  (one sub-tile, A or B)
#define STAGE_B (4*SUB_B)            // 32768 B = [A0][A1][B0][B1]
#define NSTAGE 3
#define SMEM_BYTES (NSTAGE*STAGE_B)  // 98304 B

#define KT1 42                       // 2688/64
#define KT2 34                       // 2176/64

// Scratch (__device__ globals = allowed scratch)
__device__ __half g_c[(size_t)Bsz*2688];    // fp16 [input|h_prev|m_prev]
__device__ __half g_w1[(size_t)HID*2688];   // fp16 W_h
__device__ __half g_h[(size_t)Bsz*HID];     // fp16 h
__device__ float  g_y[(size_t)Bsz*HID];     // pre-LN GEMM1 output (fp32)
__device__ float  g_u[(size_t)Bsz*256];     // stage-2 GEMM output, stride 256 (fp32)
__device__ __half g_wcat[256*2176];         // packed fp16 small weights (rows 196..255 zero)
__device__ float  g_bcat[256];

// ---------------------------------------------------------------------------
__device__ __forceinline__ void mma16(float* c, const uint32_t* a, const uint32_t* b) {
    asm volatile(
        "mma.sync.aligned.m16n8k16.row.col.f32.f16.f16.f32 "
        "{%0,%1,%2,%3}, {%4,%5,%6,%7}, {%8,%9}, {%0,%1,%2,%3};\n"
        : "+f"(c[0]), "+f"(c[1]), "+f"(c[2]), "+f"(c[3])
        : "r"(a[0]), "r"(a[1]), "r"(a[2]), "r"(a[3]), "r"(b[0]), "r"(b[1]));
}

__device__ __forceinline__ void cp_async16(char* s, const char* g) {
    uint32_t sa = (uint32_t)__cvta_generic_to_shared(s);
    asm volatile("cp.async.cg.shared.global [%0], [%1], 16;\n" :: "r"(sa), "l"(g));
}
#define CP_COMMIT() asm volatile("cp.async.commit_group;\n" ::: "memory")
#define CP_WAIT1()  asm volatile("cp.async.wait_group 1;\n" ::: "memory")

#define U4C(v, i) (((const uint32_t*)&(v))[i])

// ---------------------------------------------------------------------------
// Unified prep kernel: one launch covering
//   blocks [0, 43008)        : concat+convert inputs -> g_c
//   blocks [43008, 45696)    : convert W_h -> g_w1
//   blocks [45696, 47362)    : pack+convert small weights -> g_wcat, g_bcat
// ---------------------------------------------------------------------------
#define PREP_CONCAT_BLKS 43008
#define PREP_WH_BLKS     2688
#define PREP_PACK_BLKS   1666   // ceil(196*2176 / 256)

__global__ __launch_bounds__(256)
void prep_kernel(const float4* __restrict__ X, const float4* __restrict__ H,
                 const float4* __restrict__ M, const float4* __restrict__ W,
                 const float* Wa, const float* ba,
                 const float* Wb, const float* bb,
                 const float* Wva, const float* bva,
                 const float* Wvb, const float* bvb) {
    const int blk = blockIdx.x;
    if (blk < PREP_CONCAT_BLKS) {
        int idx = blk * 256 + threadIdx.x;          // total 16384*672 float4s
        int b = idx / 672, c = idx - b * 672;
        float4 v;
        if (c < 128)      v = X[(size_t)b * 128 + c];
        else if (c < 384) v = H[(size_t)b * 256 + (c - 128)];
        else              v = M[(size_t)b * 288 + (c - 384)];
        __half2 lo = __floats2half2_rn(v.x, v.y);
        __half2 hi = __floats2half2_rn(v.z, v.w);
        ((uint2*)g_c)[idx] = make_uint2(*(uint32_t*)&lo, *(uint32_t*)&hi);
    } else if (blk < PREP_CONCAT_BLKS + PREP_WH_BLKS) {
        int idx = (blk - PREP_CONCAT_BLKS) * 256 + threadIdx.x;  // total 1024*672
        float4 v = W[idx];
        __half2 lo = __floats2half2_rn(v.x, v.y);
        __half2 hi = __floats2half2_rn(v.z, v.w);
        ((uint2*)g_w1)[idx] = make_uint2(*(uint32_t*)&lo, *(uint32_t*)&hi);
    } else {
        int idx = (blk - PREP_CONCAT_BLKS - PREP_WH_BLKS) * 256 + threadIdx.x;
        const int total = 196 * 2176;
        if (idx < total) {
            int n = idx / 2176, k = idx - n * 2176;
            const float* src; int r;
            if (n < 2)        { src = Wa;  r = n; }
            else if (n < 4)   { src = Wb;  r = n - 2; }
            else if (n < 100) { src = Wva; r = n - 4; }
            else              { src = Wvb; r = n - 100; }
            g_wcat[n * 2176 + k] = __float2half_rn(src[(size_t)r * 2176 + k]);
        }
        if (idx < 196) {
            int n = idx;
            float v;
            if (n < 2)        v = ba[n];
            else if (n < 4)   v = bb[n - 2];
            else if (n < 100) v = bva[n - 4];
            else              v = bvb[n - 100];
            g_bcat[n] = v;
        }
    }
}

// ---------------------------------------------------------------------------
// GEMM body (R14 best): ONE __syncthreads per BK=64 tile. NSTAGE=3,
// lookahead=1: writes at iter u target stage (u+1)%3; readers hold u%3 or
// (u-1)%3 (skew <= 1 sync) — distinct mod 3. wait_group 1 => tile u resident.
#define GEMM_BODY(KT, ISSUE)                                                   \
    float acc[4][4][4];                                                        \
    _Pragma("unroll")                                                          \
    for (int i = 0; i < 4; i++)                                                \
        _Pragma("unroll")                                                      \
        for (int j = 0; j < 4; j++) {                                          \
            acc[i][j][0] = 0.f; acc[i][j][1] = 0.f;                            \
            acc[i][j][2] = 0.f; acc[i][j][3] = 0.f;                            \
        }                                                                      \
    const uint32_t offA = (wm * 64 + lr) * ROWB + lc * 16;                     \
    const uint32_t offB = 2 * SUB_B + (wn * 32 + lr) * ROWB + lc * 16;         \
    ISSUE(0); CP_COMMIT();                                                     \
    int stg_i = 0;                                                             \
    for (int t = 0; t < KT; t++) {                                             \
        if (t + 1 < KT) { ISSUE(t + 1); }                                      \
        CP_COMMIT();                                                           \
        CP_WAIT1();                                                            \
        __syncthreads();                                                       \
        const char* stg = smem + stg_i * STAGE_B;                              \
        stg_i = (stg_i == NSTAGE - 1) ? 0 : stg_i + 1;                         \
        _Pragma("unroll")                                                      \
        for (int s = 0; s < 2; s++) {                                          \
            const char* As = stg + s * SUB_B + offA;                           \
            const char* Bs = stg + s * SUB_B + offB;                           \
            uint4 av[4][2]; uint4 bv[4];                                       \
            _Pragma("unroll")                                                  \
            for (int mi = 0; mi < 4; mi++) {                                   \
                av[mi][0] = *(const uint4*)(As + mi * 16 * ROWB);              \
                av[mi][1] = *(const uint4*)(As + (mi * 16 + 8) * ROWB);        \
            }                                                                  \
            _Pragma("unroll")                                                  \
            for (int ni = 0; ni < 4; ni++)                                     \
                bv[ni] = *(const uint4*)(Bs + ni * 8 * ROWB);                  \
            _Pragma("unroll")                                                  \
            for (int j = 0; j < 2; j++) {                                      \
                _Pragma("unroll")                                              \
                for (int mi = 0; mi < 4; mi++) {                               \
                    uint32_t a[4];                                             \
                    a[0] = U4C(av[mi][0], 2 * j);                              \
                    a[1] = U4C(av[mi][1], 2 * j);                              \
                    a[2] = U4C(av[mi][0], 2 * j + 1);                          \
                    a[3] = U4C(av[mi][1], 2 * j + 1);                          \
                    _Pragma("unroll")                                          \
                    for (int ni = 0; ni < 4; ni++) {                           \
                        uint32_t b[2];                                         \
                        b[0] = U4C(bv[ni], 2 * j);                             \
                        b[1] = U4C(bv[ni], 2 * j + 1);                         \
                        mma16(acc[mi][ni], a, b);                              \
                    }                                                          \
                }                                                              \
            }                                                                  \
        }                                                                      \
    }

// ---------------------------------------------------------------------------
// GEMM1: Y = g_c @ g_w1^T + b_h   -> g_y
__global__ __launch_bounds__(256, 2)
void gemm1_kernel(const float* __restrict__ bias) {
    extern __shared__ __align__(128) char smem[];
    const int tid = threadIdx.x;
    const int bm = blockIdx.y, bn = blockIdx.x;
    const int warp = tid >> 5, lane = tid & 31;
    const int wm = warp >> 2, wn = warp & 3;
    const int lr = lane >> 2, lc = lane & 3;

    const uint32_t sOff = (tid >> 2) * ROWB + (tid & 3) * 16;
    const char* gA = (const char*)g_c  + ((size_t)(bm * BM) + (tid >> 2)) * 5376 + (tid & 3) * 16;
    const char* gB = (const char*)g_w1 + ((size_t)(bn * BN) + (tid >> 2)) * 5376 + (tid & 3) * 16;

#define ISSUE1(t) do {                                                         \
        char* st = smem + (((t) % NSTAGE)) * STAGE_B;                          \
        size_t ko = (size_t)(t) * 128;                                         \
        _Pragma("unroll")                                                      \
        for (int s = 0; s < 2; s++) {                                          \
            cp_async16(st + s * SUB_B + sOff,             gA + ko + s * 64);   \
            cp_async16(st + s * SUB_B + sOff + 64 * ROWB, gA + (size_t)64 * 5376 + ko + s * 64); \
            cp_async16(st + 2 * SUB_B + s * SUB_B + sOff, gB + ko + s * 64);   \
            cp_async16(st + 2 * SUB_B + s * SUB_B + sOff + 64 * ROWB,          \
                       gB + (size_t)64 * 5376 + ko + s * 64);                  \
        }                                                                      \
    } while (0)

    GEMM_BODY(KT1, ISSUE1)
#undef ISSUE1

    #pragma unroll
    for (int mi = 0; mi < 4; mi++) {
        #pragma unroll
        for (int ni = 0; ni < 4; ni++) {
            int r0 = bm * BM + wm * 64 + mi * 16 + lr;
            int c0 = bn * BN + wn * 32 + ni * 8 + 2 * lc;
            float b0 = bias[c0], b1 = bias[c0 + 1];
            float2 v0 = make_float2(acc[mi][ni][0] + b0, acc[mi][ni][1] + b1);
            float2 v1 = make_float2(acc[mi][ni][2] + b0, acc[mi][ni][3] + b1);
            *(float2*)&g_y[(size_t)r0 * HID + c0] = v0;
            *(float2*)&g_y[(size_t)(r0 + 8) * HID + c0] = v1;
        }
    }
}

// ---------------------------------------------------------------------------
// GEMM2: U = [g_h | g_c(m part)] @ g_wcat^T + g_bcat  -> g_u
__global__ __launch_bounds__(256, 2)
void gemm2_kernel() {
    extern __shared__ __align__(128) char smem[];
    const int tid = threadIdx.x;
    const int bm = blockIdx.y, bn = blockIdx.x;
    const int warp = tid >> 5, lane = tid & 31;
    const int wm = warp >> 2, wn = warp & 3;
    const int lr = lane >> 2, lc = lane & 3;

    const uint32_t sOff = (tid >> 2) * ROWB + (tid & 3) * 16;
    const char* gH = (const char*)g_h + ((size_t)(bm * BM) + (tid >> 2)) * 2048 + (tid & 3) * 16;
    const char* gC = (const char*)g_c + ((size_t)(bm * BM) + (tid >> 2)) * 5376 + 3072 + (tid & 3) * 16;
    const char* gW = (const char*)g_wcat + ((size_t)(bn * BN) + (tid >> 2)) * 4352 + (tid & 3) * 16;

#define ISSUE2(t) do {                                                         \
        char* st = smem + (((t) % NSTAGE)) * STAGE_B;                          \
        if ((t) < 16) {                                                        \
            size_t ko = (size_t)(t) * 128;                                     \
            _Pragma("unroll")                                                  \
            for (int s = 0; s < 2; s++) {                                      \
                cp_async16(st + s * SUB_B + sOff,             gH + ko + s * 64); \
                cp_async16(st + s * SUB_B + sOff + 64 * ROWB,                  \
                           gH + (size_t)64 * 2048 + ko + s * 64);              \
            }                                                                  \
        } else {                                                               \
            size_t ko = (size_t)((t) - 16) * 128;                              \
            _Pragma("unroll")                                                  \
            for (int s = 0; s < 2; s++) {                                      \
                cp_async16(st + s * SUB_B + sOff,             gC + ko + s * 64); \
                cp_async16(st + s * SUB_B + sOff + 64 * ROWB,                  \
                           gC + (size_t)64 * 5376 + ko + s * 64);              \
            }                                                                  \
        }                                                                      \
        size_t kw = (size_t)(t) * 128;                                         \
        _Pragma("unroll")                                                      \
        for (int s = 0; s < 2; s++) {                                          \
            cp_async16(st + 2 * SUB_B + s * SUB_B + sOff, gW + kw + s * 64);   \
            cp_async16(st + 2 * SUB_B + s * SUB_B + sOff + 64 * ROWB,          \
                       gW + (size_t)64 * 4352 + kw + s * 64);                  \
        }                                                                      \
    } while (0)

    GEMM_BODY(KT2, ISSUE2)
#undef ISSUE2

    #pragma unroll
    for (int mi = 0; mi < 4; mi++) {
        #pragma unroll
        for (int ni = 0; ni < 4; ni++) {
            int r0 = bm * BM + wm * 64 + mi * 16 + lr;
            int c0 = bn * BN + wn * 32 + ni * 8 + 2 * lc;
            float b0 = g_bcat[c0], b1 = g_bcat[c0 + 1];
            float2 v0 = make_float2(acc[mi][ni][0] + b0, acc[mi][ni][1] + b1);
            float2 v1 = make_float2(acc[mi][ni][2] + b0, acc[mi][ni][3] + b1);
            *(float2*)&g_u[(size_t)r0 * 256 + c0] = v0;
            *(float2*)&g_u[(size_t)(r0 + 8) * 256 + c0] = v1;
        }
    }
}

// ---------------------------------------------------------------------------
// LayerNorm + ReLU over rows of g_y -> hout (fp32 exact) and g_h (fp16)
__global__ __launch_bounds__(256)
void ln_relu_kernel(const float* __restrict__ g, const float* __restrict__ b,
                    float* __restrict__ hout) {
    __shared__ float sa[8], sb[8], smu[2];
    const int row = blockIdx.x, tid = threadIdx.x;
    const int lane = tid & 31, w = tid >> 5;

    float4 v = ((const float4*)(g_y + (size_t)row * HID))[tid];
    float s = v.x + v.y + v.z + v.w;
    float s2 = v.x * v.x + v.y * v.y + v.z * v.z + v.w * v.w;
    #pragma unroll
    for (int o = 16; o; o >>= 1) {
        s  += __shfl_down_sync(0xffffffffu, s, o);
        s2 += __shfl_down_sync(0xffffffffu, s2, o);
    }
    if (!lane) { sa[w] = s; sb[w] = s2; }
    __syncthreads();
    if (w == 0) {
        s  = (lane < 8) ? sa[lane] : 0.f;
        s2 = (lane < 8) ? sb[lane] : 0.f;
        #pragma unroll
        for (int o = 4; o; o >>= 1) {
            s  += __shfl_down_sync(0xffffffffu, s, o);
            s2 += __shfl_down_sync(0xffffffffu, s2, o);
        }
        if (!lane) {
            float mu = s * (1.f / HID);
            float var = s2 * (1.f / HID) - mu * mu;
            smu[0] = mu;
            smu[1] = rsqrtf(var + 1e-5f);
        }
    }
    __syncthreads();
    const float mu = smu[0], inv = smu[1];
    float4 gg = ((const float4*)g)[tid];
    float4 bb = ((const float4*)b)[tid];
    float4 o;
    o.x = fmaxf((v.x - mu) * inv * gg.x + bb.x, 0.f);
    o.y = fmaxf((v.y - mu) * inv * gg.y + bb.y, 0.f);
    o.z = fmaxf((v.z - mu) * inv * gg.z + bb.z, 0.f);
    o.w = fmaxf((v.w - mu) * inv * gg.w + bb.w, 0.f);
    ((float4*)(hout + (size_t)row * HID))[tid] = o;
    __half2 lo = __floats2half2_rn(o.x, o.y);
    __half2 hi = __floats2half2_rn(o.z, o.w);
    ((uint2*)(g_h + (size_t)row * HID))[tid] = make_uint2(*(uint32_t*)&lo, *(uint32_t*)&hi);
}

// ---------------------------------------------------------------------------
// Finalize: separable p-norm outer products -> m update
__global__ __launch_bounds__(128)
void finalize_kernel(const float* __restrict__ Mp, float* __restrict__ mout) {
    __shared__ float u[196];
    __shared__ float red[6];
    __shared__ float invn[4];
    __shared__ float cA[24], cB[24];
    const int row = blockIdx.x, tid = threadIdx.x;
    const int w = tid >> 5, lane = tid & 31;

    for (int i = tid; i < 196; i += 128) u[i] = g_u[(size_t)row * 256 + i];
    __syncthreads();

    auto p5 = [](float x) { float a = fabsf(x); float a2 = a * a; return a2 * a2 * a; };

    if (w == 0) {
        float lo = (lane < 24) ? p5(u[4 + lane]) : 0.f;
        float hi = (lane < 24) ? p5(u[4 + 24 + lane]) : 0.f;
        #pragma unroll
        for (int o = 16; o; o >>= 1) {
            lo += __shfl_down_sync(0xffffffffu, lo, o);
            hi += __shfl_down_sync(0xffffffffu, hi, o);
        }
        if (!lane) { red[0] = lo; red[1] = hi; }
    } else if (w == 1) {
        float x = p5(u[4 + 48 + lane]) + ((lane < 16) ? p5(u[4 + 80 + lane]) : 0.f);
        #pragma unroll
        for (int o = 16; o; o >>= 1) x += __shfl_down_sync(0xffffffffu, x, o);
        if (!lane) red[2] = x;
    } else if (w == 2) {
        float lo = (lane < 24) ? p5(u[100 + lane]) : 0.f;
        float hi = (lane < 24) ? p5(u[100 + 24 + lane]) : 0.f;
        #pragma unroll
        for (int o = 16; o; o >>= 1) {
            lo += __shfl_down_sync(0xffffffffu, lo, o);
            hi += __shfl_down_sync(0xffffffffu, hi, o);
        }
        if (!lane) { red[3] = lo; red[4] = hi; }
    } else {
        float x = p5(u[100 + 48 + lane]) + ((lane < 16) ? p5(u[100 + 80 + lane]) : 0.f);
        #pragma unroll
        for (int o = 16; o; o >>= 1) x += __shfl_down_sync(0xffffffffu, x, o);
        if (!lane) red[5] = x;
    }
    __syncthreads();

    if (tid < 4) {
        float s1 = (tid == 0) ? red[0] : (tid == 1) ? red[1] : (tid == 2) ? red[3] : red[4];
        float s2 = (tid < 2) ? red[2] : red[5];
        float nrm = powf(s1 * s2, 0.2f);
        invn[tid] = 1.f / fmaxf(nrm, 1e-12f);
    }
    __syncthreads();

    if (tid < 24) {
        cA[tid] = 0.5f * (u[0] * u[4 + tid] * invn[0] + u[1] * u[4 + 24 + tid] * invn[1]);
    } else if (tid >= 32 && tid < 56) {
        int i = tid - 32;
        cB[i] = 0.5f * (u[2] * u[100 + i] * invn[2] + u[3] * u[100 + 24 + i] * invn[3]);
    }
    __syncthreads();

    const float* mp = Mp + (size_t)row * MEM;
    float* mo = mout + (size_t)row * MEM;
    #pragma unroll
    for (int j = tid; j < MEM; j += 128) {
        int i = j / 48, j2 = j - i * 48;
        mo[j] = mp[j] + cA[i] * u[52 + j2] - cB[i] * u[148 + j2];
    }
}

// ---------------------------------------------------------------------------
extern "C" void kernel_launch(void* const* d_in, const int* in_sizes, int n_in,
                              void* d_out, int out_size) {
    const float* input  = (const float*)d_in[0];
    const float* h_prev = (const float*)d_in[1];
    const float* m_prev = (const float*)d_in[2];
    const float* W_h    = (const float*)d_in[3];
    const float* b_h    = (const float*)d_in[4];
    const float* ln_g   = (const float*)d_in[5];
    const float* ln_b   = (const float*)d_in[6];
    const float* W_a    = (const float*)d_in[7];
    const float* b_a    = (const float*)d_in[8];
    const float* W_b    = (const float*)d_in[9];
    const float* b_b    = (const float*)d_in[10];
    const float* W_va   = (const float*)d_in[11];
    const float* b_va   = (const float*)d_in[12];
    const float* W_vb   = (const float*)d_in[13];
    const float* b_vb   = (const float*)d_in[14];

    float* out  = (float*)d_out;
    float* hout = out;
    float* mout = out + (size_t)Bsz * HID;

    cudaFuncSetAttribute(gemm1_kernel, cudaFuncAttributeMaxDynamicSharedMemorySize, SMEM_BYTES);
    cudaFuncSetAttribute(gemm2_kernel, cudaFuncAttributeMaxDynamicSharedMemorySize, SMEM_BYTES);

    prep_kernel<<<PREP_CONCAT_BLKS + PREP_WH_BLKS + PREP_PACK_BLKS, 256>>>(
        (const float4*)input, (const float4*)h_prev, (const float4*)m_prev,
        (const float4*)W_h,
        W_a, b_a, W_b, b_b, W_va, b_va, W_vb, b_vb);
    gemm1_kernel<<<dim3(HID / BN, Bsz / BM), 256, SMEM_BYTES>>>(b_h);
    ln_relu_kernel<<<Bsz, 256>>>(ln_g, ln_b, hout);
    gemm2_kernel<<<dim3(2, Bsz / BM), 256, SMEM_BYTES>>>();
    finalize_kernel<<<Bsz, 128>>>(m_prev, mout);
}